// round 7
// baseline (speedup 1.0000x reference)
#include <cuda_runtime.h>

#define DD 128
#define NMAX 50000
#define EMAX 800000
#define SCAN_B 1024
#define SCAN_NB ((NMAX + SCAN_B - 1) / SCAN_B)   // 49

// Scratch (device globals: no allocation allowed)
__device__ float g_h[(size_t)NMAX * DD];     // GEMM output / message source
__device__ float g_agg[(size_t)NMAX * DD];   // layer-1 aggregated+relu'd features
__device__ int   g_src[EMAX];                // normalized int32 src ids
__device__ int   g_dst[EMAX];                // normalized int32 dst ids
__device__ int   g_deg[NMAX];                // degree count, then scatter cursor
__device__ int   g_off[NMAX + 1];            // CSR row offsets (by dst)
__device__ int   g_bsum[SCAN_NB + 1];        // scan block sums
__device__ int   g_nsrc[EMAX];               // dst-sorted source node ids
__device__ float g_nrm[EMAX];                // per-edge norm dinv[src]*dinv[dst]
__device__ float g_dinv[NMAX];               // (deg+1)^{-1/2}
__device__ int   g_is64;                     // 1 if edge_index is int64

// ---------------------------------------------------------------------------
// dtype detection: int64 data => every odd 32-bit word in first 2E words is 0
__global__ void init_flag_k(int* flag) {
    if (threadIdx.x == 0 && blockIdx.x == 0) *flag = 1;
}

__global__ void detect_k(const int* __restrict__ w, int E, int* flag) {
    int e = blockIdx.x * blockDim.x + threadIdx.x;
    if (e < E && w[2 * e + 1] != 0) *flag = 0;  // benign race: only writes 0
}

// Normalize edge list to int32 arrays (works for either stored dtype)
__global__ void convert_k(const void* __restrict__ ei, const int* __restrict__ flag,
                          int* __restrict__ src, int* __restrict__ dst, int E) {
    int e = blockIdx.x * blockDim.x + threadIdx.x;
    if (e >= E) return;
    if (*flag) {
        const long long* p = (const long long*)ei;
        src[e] = (int)p[e];
        dst[e] = (int)p[E + e];
    } else {
        const int* p = (const int*)ei;
        src[e] = p[e];
        dst[e] = p[E + e];
    }
}

// ---------------------------------------------------------------------------
__global__ void zero_deg_k(int* deg, int n) {
    int i = blockIdx.x * blockDim.x + threadIdx.x;
    if (i < n) deg[i] = 0;
}

__global__ void count_k(const int* __restrict__ dst, int* deg, int E) {
    int i = blockIdx.x * blockDim.x + threadIdx.x;
    if (i < E) atomicAdd(&deg[dst[i]], 1);
}

__global__ void dinv_k(const int* __restrict__ deg, float* dinv, int n) {
    int i = blockIdx.x * blockDim.x + threadIdx.x;
    if (i < n) dinv[i] = rsqrtf((float)(deg[i] + 1));  // +1 self-loop
}

// Block-wise exclusive scan of deg -> off; block totals -> bsum
__global__ void scan_block_k(const int* __restrict__ deg, int* __restrict__ off,
                             int* __restrict__ bsum, int n) {
    __shared__ int sm[SCAN_B];
    int t = threadIdx.x;
    int i = blockIdx.x * SCAN_B + t;
    int v = (i < n) ? deg[i] : 0;
    sm[t] = v;
    __syncthreads();
#pragma unroll
    for (int s = 1; s < SCAN_B; s <<= 1) {
        int add = (t >= s) ? sm[t - s] : 0;
        __syncthreads();
        sm[t] += add;
        __syncthreads();
    }
    if (i < n) off[i] = sm[t] - v;  // exclusive
    if (t == SCAN_B - 1) bsum[blockIdx.x] = sm[t];
}

__global__ void scan_bsum_k(int* bsum, int nb) {
    if (threadIdx.x == 0 && blockIdx.x == 0) {
        int run = 0;
        for (int i = 0; i < nb; i++) { int v = bsum[i]; bsum[i] = run; run += v; }
    }
}

// Add block offsets, reset cursor, set sentinel off[n] = E
__global__ void scan_add_k(int* __restrict__ off, const int* __restrict__ bsum,
                           int* __restrict__ deg, int n, int E) {
    int i = blockIdx.x * blockDim.x + threadIdx.x;
    if (i < n) {
        off[i] += bsum[i / SCAN_B];
        deg[i] = 0;  // cursor for scatter
    }
    if (i == 0) off[n] = E;
}

// Bucket edges by dst; precompute per-edge normalization
__global__ void scatter_k(const int* __restrict__ src, const int* __restrict__ dst,
                          const int* __restrict__ off, int* __restrict__ cur,
                          const float* __restrict__ dinv,
                          int* __restrict__ nsrc, float* __restrict__ nrm, int E) {
    int e = blockIdx.x * blockDim.x + threadIdx.x;
    if (e >= E) return;
    int s = src[e];
    int d = dst[e];
    int pos = off[d] + atomicAdd(&cur[d], 1);
    nsrc[pos] = s;
    nrm[pos] = dinv[s] * dinv[d];
}

// ---------------------------------------------------------------------------
// H[n,128] = X @ W[128,128]. 256 threads, 32 rows/block, W staged in 2 halves.
__global__ void gemm_k(const float* __restrict__ X, const float* __restrict__ W,
                       float* __restrict__ H, int n) {
    __shared__ float Wsm[64 * DD];  // 32 KB
    __shared__ float Xsm[32 * DD];  // 16 KB
    const int tid = threadIdx.x;
    const int row0 = blockIdx.x * 32;
    int nrows = n - row0;
    if (nrows > 32) nrows = 32;

    const float4* X4 = (const float4*)(X + (size_t)row0 * DD);
    float4* Xsm4 = (float4*)Xsm;
    for (int i = tid; i < nrows * 32; i += 256) Xsm4[i] = X4[i];

    const int c4 = tid & 31;   // float4 column
    const int rg = tid >> 5;   // row group (4 rows each)

    float4 acc[4];
#pragma unroll
    for (int r = 0; r < 4; r++) acc[r] = make_float4(0.f, 0.f, 0.f, 0.f);

    float4* Wsm4 = (float4*)Wsm;
#pragma unroll
    for (int kb = 0; kb < 2; kb++) {
        __syncthreads();
        const float4* W4 = (const float4*)(W + (size_t)kb * 64 * DD);
#pragma unroll 4
        for (int i = tid; i < 64 * 32; i += 256) Wsm4[i] = W4[i];
        __syncthreads();

        const float* xrow0 = &Xsm[(rg * 4 + 0) * DD + kb * 64];
        const float* xrow1 = &Xsm[(rg * 4 + 1) * DD + kb * 64];
        const float* xrow2 = &Xsm[(rg * 4 + 2) * DD + kb * 64];
        const float* xrow3 = &Xsm[(rg * 4 + 3) * DD + kb * 64];
#pragma unroll 16
        for (int k = 0; k < 64; k++) {
            float4 w = Wsm4[k * 32 + c4];
            float x0 = xrow0[k], x1 = xrow1[k], x2 = xrow2[k], x3 = xrow3[k];
            acc[0].x += x0 * w.x; acc[0].y += x0 * w.y; acc[0].z += x0 * w.z; acc[0].w += x0 * w.w;
            acc[1].x += x1 * w.x; acc[1].y += x1 * w.y; acc[1].z += x1 * w.z; acc[1].w += x1 * w.w;
            acc[2].x += x2 * w.x; acc[2].y += x2 * w.y; acc[2].z += x2 * w.z; acc[2].w += x2 * w.w;
            acc[3].x += x3 * w.x; acc[3].y += x3 * w.y; acc[3].z += x3 * w.z; acc[3].w += x3 * w.w;
        }
    }

    float4* H4 = (float4*)(H + (size_t)row0 * DD);
#pragma unroll
    for (int r = 0; r < 4; r++) {
        int rr = rg * 4 + r;
        if (rr < nrows) H4[rr * 32 + c4] = acc[r];
    }
}

// ---------------------------------------------------------------------------
// Warp per node: OUT[i] = relu(b + dinv[i]^2*H[i] + sum_j nrm[j]*H[nsrc[j]])
__global__ void gather_k(const int* __restrict__ off, const int* __restrict__ nsrc,
                         const float* __restrict__ nrm, const float* __restrict__ H,
                         const float* __restrict__ dinv, const float* __restrict__ b,
                         float* __restrict__ OUT, int n) {
    int gt = blockIdx.x * blockDim.x + threadIdx.x;
    int i = gt >> 5;
    if (i >= n) return;
    int lane = gt & 31;

    float s = dinv[i];
    s = s * s;
    float4 acc = ((const float4*)b)[lane];
    float4 h = ((const float4*)(H + (size_t)i * DD))[lane];
    acc.x += h.x * s; acc.y += h.y * s; acc.z += h.z * s; acc.w += h.w * s;

    int beg = off[i], end = off[i + 1];
    for (int j = beg; j < end; j++) {
        int sn = nsrc[j];     // uniform across warp -> broadcast
        float w = nrm[j];
        float4 v = ((const float4*)(H + (size_t)sn * DD))[lane];
        acc.x += v.x * w; acc.y += v.y * w; acc.z += v.z * w; acc.w += v.w * w;
    }
    acc.x = fmaxf(acc.x, 0.f); acc.y = fmaxf(acc.y, 0.f);
    acc.z = fmaxf(acc.z, 0.f); acc.w = fmaxf(acc.w, 0.f);
    ((float4*)(OUT + (size_t)i * DD))[lane] = acc;
}

// ---------------------------------------------------------------------------
extern "C" void kernel_launch(void* const* d_in, const int* in_sizes, int n_in,
                              void* d_out, int out_size) {
    const float* x   = (const float*)d_in[0];
    const void*  ei  = d_in[1];
    const float* W1  = (const float*)d_in[2];
    const float* b1  = (const float*)d_in[3];
    const float* W2  = (const float*)d_in[4];
    const float* b2  = (const float*)d_in[5];
    float* out       = (float*)d_out;

    const int n = in_sizes[0] / DD;   // 50000
    const int E = in_sizes[1] / 2;    // 800000 (element count, either dtype)

    float *h, *agg, *dinv, *nrm;
    int *src, *dst, *deg, *off, *bsum, *nsrc, *is64;
    cudaGetSymbolAddress((void**)&h, g_h);
    cudaGetSymbolAddress((void**)&agg, g_agg);
    cudaGetSymbolAddress((void**)&src, g_src);
    cudaGetSymbolAddress((void**)&dst, g_dst);
    cudaGetSymbolAddress((void**)&deg, g_deg);
    cudaGetSymbolAddress((void**)&off, g_off);
    cudaGetSymbolAddress((void**)&bsum, g_bsum);
    cudaGetSymbolAddress((void**)&nsrc, g_nsrc);
    cudaGetSymbolAddress((void**)&nrm, g_nrm);
    cudaGetSymbolAddress((void**)&dinv, g_dinv);
    cudaGetSymbolAddress((void**)&is64, g_is64);

    const int T = 256;
    const int gN    = (n + T - 1) / T;
    const int gE    = (E + T - 1) / T;
    const int gRow  = (n + 31) / 32;
    const int gWarp = (n * 32 + T - 1) / T;   // warp per node
    const int nbScan = (n + SCAN_B - 1) / SCAN_B;

    // ---- edge dtype detection + normalization to int32 ----
    init_flag_k<<<1, 32>>>(is64);
    detect_k<<<gE, T>>>((const int*)ei, E, is64);
    convert_k<<<gE, T>>>(ei, is64, src, dst, E);

    // ---- CSR build (by dst) ----
    zero_deg_k<<<gN, T>>>(deg, n);
    count_k<<<gE, T>>>(dst, deg, E);
    dinv_k<<<gN, T>>>(deg, dinv, n);
    scan_block_k<<<nbScan, SCAN_B>>>(deg, off, bsum, n);
    scan_bsum_k<<<1, 32>>>(bsum, nbScan);
    scan_add_k<<<gN, T>>>(off, bsum, deg, n, E);
    scatter_k<<<gE, T>>>(src, dst, off, deg, dinv, nsrc, nrm, E);

    // ---- layer 1 ----
    gemm_k<<<gRow, T>>>(x, W1, h, n);
    gather_k<<<gWarp, T>>>(off, nsrc, nrm, h, dinv, b1, agg, n);

    // ---- layer 2 ----
    gemm_k<<<gRow, T>>>(agg, W2, h, n);
    gather_k<<<gWarp, T>>>(off, nsrc, nrm, h, dinv, b2, out, n);
}

// round 9
// speedup vs baseline: 1.0154x; 1.0154x over previous
#include <cuda_runtime.h>

#define DD 128
#define NMAX 50000
#define EMAX 800000
#define SCAN_B 1024
#define SCAN_NB ((NMAX + SCAN_B - 1) / SCAN_B)   // 49

// Scratch (device globals: no allocation allowed)
__device__ float g_h[(size_t)NMAX * DD];     // GEMM output / message source
__device__ float g_agg[(size_t)NMAX * DD];   // layer-1 aggregated+relu'd features
__device__ int   g_src[EMAX];                // normalized int32 src ids
__device__ int   g_dst[EMAX];                // normalized int32 dst ids
__device__ int   g_deg[NMAX];                // degree count, then scatter cursor
__device__ int   g_off[NMAX + 1];            // CSR row offsets (by dst)
__device__ int   g_bsum[SCAN_NB + 1];        // scan block sums
__device__ int   g_nsrc[EMAX];               // dst-sorted source node ids
__device__ float g_nrm[EMAX];                // per-edge norm dinv[src]*dinv[dst]
__device__ float g_dinv[NMAX];               // (deg+1)^{-1/2}
__device__ int   g_is64;                     // 1 if edge_index is int64

// ---------------------------------------------------------------------------
// Zero degree counters + init dtype flag (fused)
__global__ void pre_k(int* deg, int* flag, int n) {
    int i = blockIdx.x * blockDim.x + threadIdx.x;
    if (i < n) deg[i] = 0;
    if (i == 0) *flag = 1;
}

// dtype detection: int64 data => every odd 32-bit word in first 2E words is 0
__global__ void detect_k(const int* __restrict__ w, int E, int* flag) {
    int e = blockIdx.x * blockDim.x + threadIdx.x;
    if (e < E && w[2 * e + 1] != 0) *flag = 0;  // benign race: only writes 0
}

// Normalize edge list to int32 + count in-degrees (fused)
__global__ void convert_count_k(const void* __restrict__ ei, const int* __restrict__ flag,
                                int* __restrict__ src, int* __restrict__ dst,
                                int* __restrict__ deg, int E) {
    int e = blockIdx.x * blockDim.x + threadIdx.x;
    if (e >= E) return;
    int s, d;
    if (*flag) {
        const long long* p = (const long long*)ei;
        s = (int)p[e];
        d = (int)p[E + e];
    } else {
        const int* p = (const int*)ei;
        s = p[e];
        d = p[E + e];
    }
    src[e] = s;
    dst[e] = d;
    atomicAdd(&deg[d], 1);
}

// Block-wise exclusive scan of deg -> off; block totals -> bsum
__global__ void scan_block_k(const int* __restrict__ deg, int* __restrict__ off,
                             int* __restrict__ bsum, int n) {
    __shared__ int sm[SCAN_B];
    int t = threadIdx.x;
    int i = blockIdx.x * SCAN_B + t;
    int v = (i < n) ? deg[i] : 0;
    sm[t] = v;
    __syncthreads();
#pragma unroll
    for (int s = 1; s < SCAN_B; s <<= 1) {
        int add = (t >= s) ? sm[t - s] : 0;
        __syncthreads();
        sm[t] += add;
        __syncthreads();
    }
    if (i < n) off[i] = sm[t] - v;  // exclusive
    if (t == SCAN_B - 1) bsum[blockIdx.x] = sm[t];
}

// Finish scan (each block redundantly prefixes the 49 block sums), compute
// dinv, reset cursor, set sentinel (all fused)
__global__ void scan_add_dinv_k(int* __restrict__ off, const int* __restrict__ bsum,
                                int* __restrict__ deg, float* __restrict__ dinv,
                                int n, int E, int nb) {
    __shared__ int pref[SCAN_NB];
    if (threadIdx.x == 0) {
        int run = 0;
        for (int j = 0; j < nb; j++) { pref[j] = run; run += bsum[j]; }
    }
    __syncthreads();
    int i = blockIdx.x * blockDim.x + threadIdx.x;
    if (i < n) {
        off[i] += pref[i / SCAN_B];
        dinv[i] = rsqrtf((float)(deg[i] + 1));  // +1 self-loop
        deg[i] = 0;                             // cursor for scatter
    }
    if (i == 0) off[n] = E;
}

// Bucket edges by dst; precompute per-edge normalization
__global__ void scatter_k(const int* __restrict__ src, const int* __restrict__ dst,
                          const int* __restrict__ off, int* __restrict__ cur,
                          const float* __restrict__ dinv,
                          int* __restrict__ nsrc, float* __restrict__ nrm, int E) {
    int e = blockIdx.x * blockDim.x + threadIdx.x;
    if (e >= E) return;
    int s = src[e];
    int d = dst[e];
    int pos = off[d] + atomicAdd(&cur[d], 1);
    nsrc[pos] = s;
    nrm[pos] = dinv[s] * dinv[d];
}

// ---------------------------------------------------------------------------
// H[n,128] = X @ W[128,128]. 256 threads, 64-row tile. Warp owns 8 rows;
// lane owns one float4 column. W staged in 4 quarters of 32 k-rows (16KB),
// X tile 64x128 (32KB) -> 48KB static smem. X reads are lane-uniform
// (broadcast), W reads conflict-free: ~0.5 B smem / FFMA.
__global__ void gemm_k(const float* __restrict__ X, const float* __restrict__ W,
                       float* __restrict__ H, int n) {
    __shared__ float Xsm[64 * DD];  // 32 KB
    __shared__ float Wsm[32 * DD];  // 16 KB
    const int tid = threadIdx.x;
    const int row0 = blockIdx.x * 64;
    int nrows = n - row0;
    if (nrows > 64) nrows = 64;

    const int c4 = tid & 31;        // float4 column (0..31)
    const int wr = (tid >> 5) * 8;  // warp's first row (0..56)

    // Load X tile (zero-pad tail rows so FFMA on them is harmless)
    const float4* X4 = (const float4*)(X + (size_t)row0 * DD);
    float4* Xsm4 = (float4*)Xsm;
#pragma unroll
    for (int i = tid; i < 64 * 32; i += 256) {
        float4 v = make_float4(0.f, 0.f, 0.f, 0.f);
        if ((i >> 5) < nrows) v = X4[i];
        Xsm4[i] = v;
    }

    float4 acc[8];
#pragma unroll
    for (int r = 0; r < 8; r++) acc[r] = make_float4(0.f, 0.f, 0.f, 0.f);

    float4* Wsm4 = (float4*)Wsm;
#pragma unroll
    for (int kb = 0; kb < 4; kb++) {
        __syncthreads();
        const float4* W4 = (const float4*)(W + (size_t)kb * 32 * DD);
#pragma unroll
        for (int i = tid; i < 32 * 32; i += 256) Wsm4[i] = W4[i];
        __syncthreads();

#pragma unroll
        for (int k4 = 0; k4 < 8; k4++) {   // 8 chunks of 4 k-values
            float4 xr[8];
#pragma unroll
            for (int r = 0; r < 8; r++)
                xr[r] = Xsm4[(wr + r) * 32 + kb * 8 + k4];  // lane-uniform
#pragma unroll
            for (int kk = 0; kk < 4; kk++) {
                float4 wv = Wsm4[(k4 * 4 + kk) * 32 + c4];
#pragma unroll
                for (int r = 0; r < 8; r++) {
                    float xv = (kk == 0) ? xr[r].x : (kk == 1) ? xr[r].y
                             : (kk == 2) ? xr[r].z : xr[r].w;
                    acc[r].x += xv * wv.x; acc[r].y += xv * wv.y;
                    acc[r].z += xv * wv.z; acc[r].w += xv * wv.w;
                }
            }
        }
    }

    float4* H4 = (float4*)(H + (size_t)row0 * DD);
#pragma unroll
    for (int r = 0; r < 8; r++) {
        int rr = wr + r;
        if (rr < nrows) H4[rr * 32 + c4] = acc[r];
    }
}

// ---------------------------------------------------------------------------
// Warp per node: OUT[i] = relu(b + dinv[i]^2*H[i] + sum_j nrm[j]*H[nsrc[j]])
// Unroll-by-2 with dual accumulators for deeper L2 MLP.
__global__ void gather_k(const int* __restrict__ off, const int* __restrict__ nsrc,
                         const float* __restrict__ nrm, const float* __restrict__ H,
                         const float* __restrict__ dinv, const float* __restrict__ b,
                         float* __restrict__ OUT, int n) {
    int gt = blockIdx.x * blockDim.x + threadIdx.x;
    int i = gt >> 5;
    if (i >= n) return;
    int lane = gt & 31;

    float s = __ldg(&dinv[i]);
    s = s * s;
    float4 acc0 = __ldg(((const float4*)b) + lane);
    float4 h = __ldg(((const float4*)(H + (size_t)i * DD)) + lane);
    acc0.x += h.x * s; acc0.y += h.y * s; acc0.z += h.z * s; acc0.w += h.w * s;
    float4 acc1 = make_float4(0.f, 0.f, 0.f, 0.f);

    int beg = off[i], end = off[i + 1];
    int j = beg;
    for (; j + 2 <= end; j += 2) {
        int   s0 = __ldg(&nsrc[j]);
        int   s1 = __ldg(&nsrc[j + 1]);
        float w0 = __ldg(&nrm[j]);
        float w1 = __ldg(&nrm[j + 1]);
        float4 v0 = __ldg(((const float4*)(H + (size_t)s0 * DD)) + lane);
        float4 v1 = __ldg(((const float4*)(H + (size_t)s1 * DD)) + lane);
        acc0.x += v0.x * w0; acc0.y += v0.y * w0; acc0.z += v0.z * w0; acc0.w += v0.w * w0;
        acc1.x += v1.x * w1; acc1.y += v1.y * w1; acc1.z += v1.z * w1; acc1.w += v1.w * w1;
    }
    if (j < end) {
        int   s0 = __ldg(&nsrc[j]);
        float w0 = __ldg(&nrm[j]);
        float4 v0 = __ldg(((const float4*)(H + (size_t)s0 * DD)) + lane);
        acc0.x += v0.x * w0; acc0.y += v0.y * w0; acc0.z += v0.z * w0; acc0.w += v0.w * w0;
    }
    acc0.x = fmaxf(acc0.x + acc1.x, 0.f);
    acc0.y = fmaxf(acc0.y + acc1.y, 0.f);
    acc0.z = fmaxf(acc0.z + acc1.z, 0.f);
    acc0.w = fmaxf(acc0.w + acc1.w, 0.f);
    ((float4*)(OUT + (size_t)i * DD))[lane] = acc0;
}

// ---------------------------------------------------------------------------
extern "C" void kernel_launch(void* const* d_in, const int* in_sizes, int n_in,
                              void* d_out, int out_size) {
    const float* x   = (const float*)d_in[0];
    const void*  ei  = d_in[1];
    const float* W1  = (const float*)d_in[2];
    const float* b1  = (const float*)d_in[3];
    const float* W2  = (const float*)d_in[4];
    const float* b2  = (const float*)d_in[5];
    float* out       = (float*)d_out;

    const int n = in_sizes[0] / DD;   // 50000
    const int E = in_sizes[1] / 2;    // 800000 (element count, either dtype)

    float *h, *agg, *dinv, *nrm;
    int *src, *dst, *deg, *off, *bsum, *nsrc, *is64;
    cudaGetSymbolAddress((void**)&h, g_h);
    cudaGetSymbolAddress((void**)&agg, g_agg);
    cudaGetSymbolAddress((void**)&src, g_src);
    cudaGetSymbolAddress((void**)&dst, g_dst);
    cudaGetSymbolAddress((void**)&deg, g_deg);
    cudaGetSymbolAddress((void**)&off, g_off);
    cudaGetSymbolAddress((void**)&bsum, g_bsum);
    cudaGetSymbolAddress((void**)&nsrc, g_nsrc);
    cudaGetSymbolAddress((void**)&nrm, g_nrm);
    cudaGetSymbolAddress((void**)&dinv, g_dinv);
    cudaGetSymbolAddress((void**)&is64, g_is64);

    const int T = 256;
    const int gN    = (n + T - 1) / T;
    const int gE    = (E + T - 1) / T;
    const int gRow  = (n + 63) / 64;          // 64-row gemm tiles
    const int gWarp = (n * 32 + T - 1) / T;   // warp per node
    const int nbScan = (n + SCAN_B - 1) / SCAN_B;

    // ---- edge dtype normalization + CSR build (by dst) ----
    pre_k<<<gN, T>>>(deg, is64, n);
    detect_k<<<gE, T>>>((const int*)ei, E, is64);
    convert_count_k<<<gE, T>>>(ei, is64, src, dst, deg, E);
    scan_block_k<<<nbScan, SCAN_B>>>(deg, off, bsum, n);
    scan_add_dinv_k<<<gN, T>>>(off, bsum, deg, dinv, n, E, nbScan);
    scatter_k<<<gE, T>>>(src, dst, off, deg, dinv, nsrc, nrm, E);

    // ---- layer 1 ----
    gemm_k<<<gRow, T>>>(x, W1, h, n);
    gather_k<<<gWarp, T>>>(off, nsrc, nrm, h, dinv, b1, agg, n);

    // ---- layer 2 ----
    gemm_k<<<gRow, T>>>(agg, W2, h, n);
    gather_k<<<gWarp, T>>>(off, nsrc, nrm, h, dinv, b2, out, n);
}

// round 10
// speedup vs baseline: 1.3041x; 1.2843x over previous
#include <cuda_runtime.h>
#include <cstdint>

#define DD 128
#define NMAX 50000
#define EMAX 800000
#define SCAN_B 1024
#define SCAN_NB ((NMAX + SCAN_B - 1) / SCAN_B)   // 49

// Scratch (device globals: no allocation allowed)
__device__ float g_h[(size_t)NMAX * DD];     // GEMM output / message source
__device__ float g_agg[(size_t)NMAX * DD];   // layer-1 aggregated+relu'd features
__device__ int   g_deg[NMAX];                // degree count, then scatter cursor
__device__ int   g_off[NMAX + 1];            // CSR row offsets (by dst)
__device__ int   g_bsum[SCAN_NB + 1];        // scan block sums
__device__ int   g_nsrc[EMAX];               // dst-sorted source node ids
__device__ float g_nrm[EMAX];                // per-edge norm dinv[src]*dinv[dst]
__device__ float g_dinv[NMAX];               // (deg+1)^{-1/2}
__device__ int   g_is64;                     // 1 if edge_index is int64
__device__ uint2 g_wf1[16 * 16 * 32];        // W1 tf32 b-fragments (64KB)
__device__ uint2 g_wf2[16 * 16 * 32];        // W2 tf32 b-fragments

__device__ __forceinline__ uint32_t f2tf32(float f) {
    uint32_t o;
    asm("cvt.rna.tf32.f32 %0, %1;" : "=r"(o) : "f"(f));
    return o;
}

__device__ __forceinline__ int edge_id(const void* ei, const int* flag, int idx) {
    // idx in [0, 2E): src then dst halves
    if (*flag) return (int)((const long long*)ei)[idx];
    return ((const int*)ei)[idx];
}

// ---------------------------------------------------------------------------
// Zero degree counters + init dtype flag (fused)
__global__ void pre_k(int* deg, int* flag, int n) {
    int i = blockIdx.x * blockDim.x + threadIdx.x;
    if (i < n) deg[i] = 0;
    if (i == 0) *flag = 1;
}

// dtype detection: int64 data => every odd 32-bit word in first 2E words is 0
__global__ void detect_k(const int* __restrict__ w, int E, int* flag) {
    int e = blockIdx.x * blockDim.x + threadIdx.x;
    if (e < E && w[2 * e + 1] != 0) *flag = 0;  // benign race: only writes 0
}

// Count in-degrees straight from the edge buffer
__global__ void count_k(const void* __restrict__ ei, const int* __restrict__ flag,
                        int* __restrict__ deg, int E) {
    int e = blockIdx.x * blockDim.x + threadIdx.x;
    if (e < E) atomicAdd(&deg[edge_id(ei, flag, E + e)], 1);
}

// Block-wise exclusive scan of deg -> off; block totals -> bsum
__global__ void scan_block_k(const int* __restrict__ deg, int* __restrict__ off,
                             int* __restrict__ bsum, int n) {
    __shared__ int sm[SCAN_B];
    int t = threadIdx.x;
    int i = blockIdx.x * SCAN_B + t;
    int v = (i < n) ? deg[i] : 0;
    sm[t] = v;
    __syncthreads();
#pragma unroll
    for (int s = 1; s < SCAN_B; s <<= 1) {
        int add = (t >= s) ? sm[t - s] : 0;
        __syncthreads();
        sm[t] += add;
        __syncthreads();
    }
    if (i < n) off[i] = sm[t] - v;  // exclusive
    if (t == SCAN_B - 1) bsum[blockIdx.x] = sm[t];
}

// Finish scan, compute dinv, reset cursor, set sentinel (fused)
__global__ void scan_add_dinv_k(int* __restrict__ off, const int* __restrict__ bsum,
                                int* __restrict__ deg, float* __restrict__ dinv,
                                int n, int E, int nb) {
    __shared__ int pref[SCAN_NB];
    if (threadIdx.x == 0) {
        int run = 0;
        for (int j = 0; j < nb; j++) { pref[j] = run; run += bsum[j]; }
    }
    __syncthreads();
    int i = blockIdx.x * blockDim.x + threadIdx.x;
    if (i < n) {
        off[i] += pref[i / SCAN_B];
        dinv[i] = rsqrtf((float)(deg[i] + 1));  // +1 self-loop
        deg[i] = 0;                             // cursor for scatter
    }
    if (i == 0) off[n] = E;
}

// Bucket edges by dst; precompute per-edge normalization
__global__ void scatter_k(const void* __restrict__ ei, const int* __restrict__ flag,
                          const int* __restrict__ off, int* __restrict__ cur,
                          const float* __restrict__ dinv,
                          int* __restrict__ nsrc, float* __restrict__ nrm, int E) {
    int e = blockIdx.x * blockDim.x + threadIdx.x;
    if (e >= E) return;
    int s = edge_id(ei, flag, e);
    int d = edge_id(ei, flag, E + e);
    int pos = off[d] + atomicAdd(&cur[d], 1);
    nsrc[pos] = s;
    nrm[pos] = dinv[s] * dinv[d];
}

// ---------------------------------------------------------------------------
// Pre-swizzle W[128k][128n] into mma b-fragment layout:
// wf[((kstep*16 + ntile)*32 + lane)] = { tf32 W[ks*8+tig][nt*8+gid],
//                                        tf32 W[ks*8+tig+4][nt*8+gid] }
__global__ void wfrag_k(const float* __restrict__ W, uint2* __restrict__ wf) {
    int idx = blockIdx.x * blockDim.x + threadIdx.x;
    if (idx >= 16 * 16 * 32) return;
    int lane = idx & 31;
    int nt = (idx >> 5) & 15;
    int ks = idx >> 9;
    int tig = lane & 3, gid = lane >> 2;
    int nn = nt * 8 + gid;
    int k0 = ks * 8 + tig;
    wf[idx] = make_uint2(f2tf32(W[k0 * DD + nn]), f2tf32(W[(k0 + 4) * DD + nn]));
}

// H[n,128] = X @ W via mma.sync.m16n8k8 tf32.
// 256 threads (8 warps), 128 rows/block; warp owns 16 rows x 128 cols.
// W fragments staged in smem in two 32KB halves (k-steps 0..7, 8..15).
__global__ __launch_bounds__(256) void gemm_tf32_k(const float* __restrict__ X,
                                                   const uint2* __restrict__ wf,
                                                   float* __restrict__ H, int n) {
    __shared__ uint2 Wsm[8 * 16 * 32];  // 32 KB
    const int tid = threadIdx.x;
    const int wid = tid >> 5;
    const int lane = tid & 31;
    const int tig = lane & 3, gid = lane >> 2;

    const int row0 = blockIdx.x * 128 + wid * 16 + gid;  // this thread: row0, row0+8
    const int r0 = min(row0, n - 1);
    const int r1 = min(row0 + 8, n - 1);
    const float* x0 = X + (size_t)r0 * DD;
    const float* x1 = X + (size_t)r1 * DD;

    float c[16][4];
#pragma unroll
    for (int nt = 0; nt < 16; nt++)
#pragma unroll
        for (int q = 0; q < 4; q++) c[nt][q] = 0.f;

#pragma unroll
    for (int half = 0; half < 2; half++) {
        __syncthreads();
        const uint4* srcp = (const uint4*)(wf + half * 4096);
        uint4* dstp = (uint4*)Wsm;
#pragma unroll
        for (int i = tid; i < 2048; i += 256) dstp[i] = srcp[i];
        __syncthreads();

#pragma unroll
        for (int ks = 0; ks < 8; ks++) {
            const int k = half * 64 + ks * 8;
            uint32_t a0 = f2tf32(x0[k + tig]);
            uint32_t a1 = f2tf32(x1[k + tig]);
            uint32_t a2 = f2tf32(x0[k + tig + 4]);
            uint32_t a3 = f2tf32(x1[k + tig + 4]);
#pragma unroll
            for (int nt = 0; nt < 16; nt++) {
                uint2 b = Wsm[(ks * 16 + nt) * 32 + lane];
                asm volatile(
                    "mma.sync.aligned.m16n8k8.row.col.f32.tf32.tf32.f32 "
                    "{%0,%1,%2,%3}, {%4,%5,%6,%7}, {%8,%9}, {%0,%1,%2,%3};"
                    : "+f"(c[nt][0]), "+f"(c[nt][1]), "+f"(c[nt][2]), "+f"(c[nt][3])
                    : "r"(a0), "r"(a1), "r"(a2), "r"(a3), "r"(b.x), "r"(b.y));
            }
        }
    }

    // store: c0,c1 -> row0, cols nt*8 + 2*tig; c2,c3 -> row0+8
    if (row0 < n) {
        float2* p = (float2*)(H + (size_t)row0 * DD);
#pragma unroll
        for (int nt = 0; nt < 16; nt++)
            p[nt * 4 + tig] = make_float2(c[nt][0], c[nt][1]);
    }
    if (row0 + 8 < n) {
        float2* p = (float2*)(H + (size_t)(row0 + 8) * DD);
#pragma unroll
        for (int nt = 0; nt < 16; nt++)
            p[nt * 4 + tig] = make_float2(c[nt][2], c[nt][3]);
    }
}

// ---------------------------------------------------------------------------
// Warp per node: OUT[i] = relu(b + dinv[i]^2*H[i] + sum_j nrm[j]*H[nsrc[j]])
__global__ void gather_k(const int* __restrict__ off, const int* __restrict__ nsrc,
                         const float* __restrict__ nrm, const float* __restrict__ H,
                         const float* __restrict__ dinv, const float* __restrict__ b,
                         float* __restrict__ OUT, int n) {
    int gt = blockIdx.x * blockDim.x + threadIdx.x;
    int i = gt >> 5;
    if (i >= n) return;
    int lane = gt & 31;

    float s = __ldg(&dinv[i]);
    s = s * s;
    float4 acc0 = __ldg(((const float4*)b) + lane);
    float4 h = __ldg(((const float4*)(H + (size_t)i * DD)) + lane);
    acc0.x += h.x * s; acc0.y += h.y * s; acc0.z += h.z * s; acc0.w += h.w * s;
    float4 acc1 = make_float4(0.f, 0.f, 0.f, 0.f);

    int beg = off[i], end = off[i + 1];
    int j = beg;
    for (; j + 2 <= end; j += 2) {
        int   s0 = __ldg(&nsrc[j]);
        int   s1 = __ldg(&nsrc[j + 1]);
        float w0 = __ldg(&nrm[j]);
        float w1 = __ldg(&nrm[j + 1]);
        float4 v0 = __ldg(((const float4*)(H + (size_t)s0 * DD)) + lane);
        float4 v1 = __ldg(((const float4*)(H + (size_t)s1 * DD)) + lane);
        acc0.x += v0.x * w0; acc0.y += v0.y * w0; acc0.z += v0.z * w0; acc0.w += v0.w * w0;
        acc1.x += v1.x * w1; acc1.y += v1.y * w1; acc1.z += v1.z * w1; acc1.w += v1.w * w1;
    }
    if (j < end) {
        int   s0 = __ldg(&nsrc[j]);
        float w0 = __ldg(&nrm[j]);
        float4 v0 = __ldg(((const float4*)(H + (size_t)s0 * DD)) + lane);
        acc0.x += v0.x * w0; acc0.y += v0.y * w0; acc0.z += v0.z * w0; acc0.w += v0.w * w0;
    }
    acc0.x = fmaxf(acc0.x + acc1.x, 0.f);
    acc0.y = fmaxf(acc0.y + acc1.y, 0.f);
    acc0.z = fmaxf(acc0.z + acc1.z, 0.f);
    acc0.w = fmaxf(acc0.w + acc1.w, 0.f);
    ((float4*)(OUT + (size_t)i * DD))[lane] = acc0;
}

// ---------------------------------------------------------------------------
extern "C" void kernel_launch(void* const* d_in, const int* in_sizes, int n_in,
                              void* d_out, int out_size) {
    const float* x   = (const float*)d_in[0];
    const void*  ei  = d_in[1];
    const float* W1  = (const float*)d_in[2];
    const float* b1  = (const float*)d_in[3];
    const float* W2  = (const float*)d_in[4];
    const float* b2  = (const float*)d_in[5];
    float* out       = (float*)d_out;

    const int n = in_sizes[0] / DD;   // 50000
    const int E = in_sizes[1] / 2;    // 800000 (element count, either dtype)

    float *h, *agg, *dinv, *nrm;
    int *deg, *off, *bsum, *nsrc, *is64;
    uint2 *wf1, *wf2;
    cudaGetSymbolAddress((void**)&h, g_h);
    cudaGetSymbolAddress((void**)&agg, g_agg);
    cudaGetSymbolAddress((void**)&deg, g_deg);
    cudaGetSymbolAddress((void**)&off, g_off);
    cudaGetSymbolAddress((void**)&bsum, g_bsum);
    cudaGetSymbolAddress((void**)&nsrc, g_nsrc);
    cudaGetSymbolAddress((void**)&nrm, g_nrm);
    cudaGetSymbolAddress((void**)&dinv, g_dinv);
    cudaGetSymbolAddress((void**)&is64, g_is64);
    cudaGetSymbolAddress((void**)&wf1, g_wf1);
    cudaGetSymbolAddress((void**)&wf2, g_wf2);

    const int T = 256;
    const int gN    = (n + T - 1) / T;
    const int gE    = (E + T - 1) / T;
    const int gRowT = (n + 127) / 128;        // tf32 gemm tiles
    const int gWarp = (n * 32 + T - 1) / T;   // warp per node
    const int nbScan = (n + SCAN_B - 1) / SCAN_B;

    // ---- edge dtype detection + CSR build (by dst) ----
    pre_k<<<gN, T>>>(deg, is64, n);
    detect_k<<<gE, T>>>((const int*)ei, E, is64);
    count_k<<<gE, T>>>(ei, is64, deg, E);
    scan_block_k<<<nbScan, SCAN_B>>>(deg, off, bsum, n);
    scan_add_dinv_k<<<gN, T>>>(off, bsum, deg, dinv, n, E, nbScan);
    scatter_k<<<gE, T>>>(ei, is64, off, deg, dinv, nsrc, nrm, E);

    // ---- weight fragment pre-swizzle (independent of edges) ----
    wfrag_k<<<32, T>>>(W1, wf1);
    wfrag_k<<<32, T>>>(W2, wf2);

    // ---- layer 1 ----
    gemm_tf32_k<<<gRowT, T>>>(x, wf1, h, n);
    gather_k<<<gWarp, T>>>(off, nsrc, nrm, h, dinv, b1, agg, n);

    // ---- layer 2 ----
    gemm_tf32_k<<<gRowT, T>>>(agg, wf2, h, n);
    gather_k<<<gWarp, T>>>(off, nsrc, nrm, h, dinv, b2, out, n);
}

// round 11
// speedup vs baseline: 1.3378x; 1.0258x over previous
#include <cuda_runtime.h>
#include <cuda_fp16.h>
#include <cstdint>

#define DD 128
#define NMAX 50000
#define EMAX 800000
#define SCAN_B 1024
#define SCAN_NB ((NMAX + SCAN_B - 1) / SCAN_B)   // 49

// Scratch (device globals: no allocation allowed)
__device__ __half g_h[(size_t)NMAX * DD];    // GEMM output in fp16 (12.8MB)
__device__ float g_agg[(size_t)NMAX * DD];   // layer-1 aggregated+relu'd features
__device__ int   g_deg[NMAX];                // degree count, then scatter cursor
__device__ int   g_off[NMAX + 1];            // CSR row offsets (by dst)
__device__ int   g_bsum[SCAN_NB + 1];        // scan block sums
__device__ int   g_nsrc[EMAX];               // dst-sorted source node ids
__device__ float g_nrm[EMAX];                // per-edge norm dinv[src]*dinv[dst]
__device__ float g_dinv[NMAX];               // (deg+1)^{-1/2}
__device__ int   g_is64;                     // 1 if edge_index is int64
__device__ uint2 g_wf1[16 * 16 * 32];        // W1 tf32 b-fragments (64KB)
__device__ uint2 g_wf2[16 * 16 * 32];        // W2 tf32 b-fragments

__device__ __forceinline__ uint32_t f2tf32(float f) {
    uint32_t o;
    asm("cvt.rna.tf32.f32 %0, %1;" : "=r"(o) : "f"(f));
    return o;
}

__device__ __forceinline__ int edge_id(const void* ei, const int* flag, int idx) {
    if (*flag) return (int)((const long long*)ei)[idx];
    return ((const int*)ei)[idx];
}

// ---------------------------------------------------------------------------
__global__ void pre_k(int* deg, int* flag, int n) {
    int i = blockIdx.x * blockDim.x + threadIdx.x;
    if (i < n) deg[i] = 0;
    if (i == 0) *flag = 1;
}

// dtype detection: int64 data => every odd 32-bit word in first 2E words is 0
__global__ void detect_k(const int* __restrict__ w, int E, int* flag) {
    int e = blockIdx.x * blockDim.x + threadIdx.x;
    if (e < E && w[2 * e + 1] != 0) *flag = 0;  // benign race: only writes 0
}

__global__ void count_k(const void* __restrict__ ei, const int* __restrict__ flag,
                        int* __restrict__ deg, int E) {
    int e = blockIdx.x * blockDim.x + threadIdx.x;
    if (e < E) atomicAdd(&deg[edge_id(ei, flag, E + e)], 1);
}

// Block-wise exclusive scan of deg -> off (shfl-based); block totals -> bsum
__global__ void scan_block_k(const int* __restrict__ deg, int* __restrict__ off,
                             int* __restrict__ bsum, int n) {
    __shared__ int wsum[32];
    int t = threadIdx.x;
    int i = blockIdx.x * SCAN_B + t;
    int v = (i < n) ? deg[i] : 0;
    int lane = t & 31, w = t >> 5;

    int s = v;  // inclusive warp scan
#pragma unroll
    for (int d = 1; d < 32; d <<= 1) {
        int x = __shfl_up_sync(0xFFFFFFFFu, s, d);
        if (lane >= d) s += x;
    }
    if (lane == 31) wsum[w] = s;
    __syncthreads();
    if (w == 0) {
        int ws = wsum[lane];
#pragma unroll
        for (int d = 1; d < 32; d <<= 1) {
            int x = __shfl_up_sync(0xFFFFFFFFu, ws, d);
            if (lane >= d) ws += x;
        }
        wsum[lane] = ws;
    }
    __syncthreads();
    int incl = s + ((w > 0) ? wsum[w - 1] : 0);
    if (i < n) off[i] = incl - v;  // exclusive
    if (t == SCAN_B - 1) bsum[blockIdx.x] = incl;
}

// Finish scan, compute dinv, reset cursor, set sentinel (fused)
__global__ void scan_add_dinv_k(int* __restrict__ off, const int* __restrict__ bsum,
                                int* __restrict__ deg, float* __restrict__ dinv,
                                int n, int E, int nb) {
    __shared__ int pref[SCAN_NB];
    if (threadIdx.x == 0) {
        int run = 0;
        for (int j = 0; j < nb; j++) { pref[j] = run; run += bsum[j]; }
    }
    __syncthreads();
    int i = blockIdx.x * blockDim.x + threadIdx.x;
    if (i < n) {
        off[i] += pref[i / SCAN_B];
        dinv[i] = rsqrtf((float)(deg[i] + 1));  // +1 self-loop
        deg[i] = 0;                             // cursor for scatter
    }
    if (i == 0) off[n] = E;
}

// Bucket edges by dst; precompute per-edge normalization
__global__ void scatter_k(const void* __restrict__ ei, const int* __restrict__ flag,
                          const int* __restrict__ off, int* __restrict__ cur,
                          const float* __restrict__ dinv,
                          int* __restrict__ nsrc, float* __restrict__ nrm, int E) {
    int e = blockIdx.x * blockDim.x + threadIdx.x;
    if (e >= E) return;
    int s = edge_id(ei, flag, e);
    int d = edge_id(ei, flag, E + e);
    int pos = off[d] + atomicAdd(&cur[d], 1);
    nsrc[pos] = s;
    nrm[pos] = dinv[s] * dinv[d];
}

// ---------------------------------------------------------------------------
// Pre-swizzle both W matrices into mma b-fragment layout (fused launch).
__global__ void wfrag_k(const float* __restrict__ W1, const float* __restrict__ W2,
                        uint2* __restrict__ wf1, uint2* __restrict__ wf2) {
    int idx = blockIdx.x * blockDim.x + threadIdx.x;
    const float* W = (idx < 8192) ? W1 : W2;
    uint2* wf = (idx < 8192) ? wf1 : wf2;
    int id = idx & 8191;
    if (idx >= 16384) return;
    int lane = id & 31;
    int nt = (id >> 5) & 15;
    int ks = id >> 9;
    int tig = lane & 3, gid = lane >> 2;
    int nn = nt * 8 + gid;
    int k0 = ks * 8 + tig;
    wf[id] = make_uint2(f2tf32(W[k0 * DD + nn]), f2tf32(W[(k0 + 4) * DD + nn]));
}

// H[n,128] = X @ W via mma.sync.m16n8k8 tf32; output stored as fp16.
__global__ __launch_bounds__(256) void gemm_tf32_k(const float* __restrict__ X,
                                                   const uint2* __restrict__ wf,
                                                   __half* __restrict__ H, int n) {
    __shared__ uint2 Wsm[8 * 16 * 32];  // 32 KB
    const int tid = threadIdx.x;
    const int wid = tid >> 5;
    const int lane = tid & 31;
    const int tig = lane & 3, gid = lane >> 2;

    const int row0 = blockIdx.x * 128 + wid * 16 + gid;  // this thread: row0, row0+8
    const int r0 = min(row0, n - 1);
    const int r1 = min(row0 + 8, n - 1);
    const float* x0 = X + (size_t)r0 * DD;
    const float* x1 = X + (size_t)r1 * DD;

    float c[16][4];
#pragma unroll
    for (int nt = 0; nt < 16; nt++)
#pragma unroll
        for (int q = 0; q < 4; q++) c[nt][q] = 0.f;

#pragma unroll
    for (int half = 0; half < 2; half++) {
        __syncthreads();
        const uint4* srcp = (const uint4*)(wf + half * 4096);
        uint4* dstp = (uint4*)Wsm;
#pragma unroll
        for (int i = tid; i < 2048; i += 256) dstp[i] = srcp[i];
        __syncthreads();

#pragma unroll
        for (int ks = 0; ks < 8; ks++) {
            const int k = half * 64 + ks * 8;
            uint32_t a0 = f2tf32(x0[k + tig]);
            uint32_t a1 = f2tf32(x1[k + tig]);
            uint32_t a2 = f2tf32(x0[k + tig + 4]);
            uint32_t a3 = f2tf32(x1[k + tig + 4]);
#pragma unroll
            for (int nt = 0; nt < 16; nt++) {
                uint2 b = Wsm[(ks * 16 + nt) * 32 + lane];
                asm volatile(
                    "mma.sync.aligned.m16n8k8.row.col.f32.tf32.tf32.f32 "
                    "{%0,%1,%2,%3}, {%4,%5,%6,%7}, {%8,%9}, {%0,%1,%2,%3};"
                    : "+f"(c[nt][0]), "+f"(c[nt][1]), "+f"(c[nt][2]), "+f"(c[nt][3])
                    : "r"(a0), "r"(a1), "r"(a2), "r"(a3), "r"(b.x), "r"(b.y));
            }
        }
    }

    // store: thread owns half2 slot nt*4+tig of each of its 2 rows
    if (row0 < n) {
        __half2* p = (__half2*)(H + (size_t)row0 * DD);
#pragma unroll
        for (int nt = 0; nt < 16; nt++)
            p[nt * 4 + tig] = __floats2half2_rn(c[nt][0], c[nt][1]);
    }
    if (row0 + 8 < n) {
        __half2* p = (__half2*)(H + (size_t)(row0 + 8) * DD);
#pragma unroll
        for (int nt = 0; nt < 16; nt++)
            p[nt * 4 + tig] = __floats2half2_rn(c[nt][2], c[nt][3]);
    }
}

// ---------------------------------------------------------------------------
// Warp per node, H in fp16: lane loads uint2 (4 halves) per edge -> warp
// covers the full 256B row in one LDG.64/lane. fp32 accumulation.
__global__ void gather_k(const int* __restrict__ off, const int* __restrict__ nsrc,
                         const float* __restrict__ nrm, const __half* __restrict__ H,
                         const float* __restrict__ dinv, const float* __restrict__ b,
                         float* __restrict__ OUT, int n) {
    int gt = blockIdx.x * blockDim.x + threadIdx.x;
    int i = gt >> 5;
    if (i >= n) return;
    int lane = gt & 31;

    float s = __ldg(&dinv[i]);
    s = s * s;
    float4 acc0 = __ldg(((const float4*)b) + lane);
    {
        const __half2* hp = (const __half2*)(H + (size_t)i * DD);
        float2 h0 = __half22float2(__ldg(hp + lane * 2));
        float2 h1 = __half22float2(__ldg(hp + lane * 2 + 1));
        acc0.x += h0.x * s; acc0.y += h0.y * s;
        acc0.z += h1.x * s; acc0.w += h1.y * s;
    }
    float4 acc1 = make_float4(0.f, 0.f, 0.f, 0.f);

    int beg = off[i], end = off[i + 1];
    int j = beg;
    for (; j + 2 <= end; j += 2) {
        int   s0 = __ldg(&nsrc[j]);
        int   s1 = __ldg(&nsrc[j + 1]);
        float w0 = __ldg(&nrm[j]);
        float w1 = __ldg(&nrm[j + 1]);
        const __half2* p0 = ((const __half2*)(H + (size_t)s0 * DD)) + lane * 2;
        const __half2* p1 = ((const __half2*)(H + (size_t)s1 * DD)) + lane * 2;
        __half2 a0 = __ldg(p0), b0 = __ldg(p0 + 1);
        __half2 a1 = __ldg(p1), b1 = __ldg(p1 + 1);
        float2 f0 = __half22float2(a0), g0 = __half22float2(b0);
        float2 f1 = __half22float2(a1), g1 = __half22float2(b1);
        acc0.x += f0.x * w0; acc0.y += f0.y * w0; acc0.z += g0.x * w0; acc0.w += g0.y * w0;
        acc1.x += f1.x * w1; acc1.y += f1.y * w1; acc1.z += g1.x * w1; acc1.w += g1.y * w1;
    }
    if (j < end) {
        int   s0 = __ldg(&nsrc[j]);
        float w0 = __ldg(&nrm[j]);
        const __half2* p0 = ((const __half2*)(H + (size_t)s0 * DD)) + lane * 2;
        float2 f0 = __half22float2(__ldg(p0));
        float2 g0 = __half22float2(__ldg(p0 + 1));
        acc0.x += f0.x * w0; acc0.y += f0.y * w0; acc0.z += g0.x * w0; acc0.w += g0.y * w0;
    }
    acc0.x = fmaxf(acc0.x + acc1.x, 0.f);
    acc0.y = fmaxf(acc0.y + acc1.y, 0.f);
    acc0.z = fmaxf(acc0.z + acc1.z, 0.f);
    acc0.w = fmaxf(acc0.w + acc1.w, 0.f);
    // lane owns cols lane*4..lane*4+3
    ((float4*)(OUT + (size_t)i * DD))[lane] = acc0;
}

// ---------------------------------------------------------------------------
extern "C" void kernel_launch(void* const* d_in, const int* in_sizes, int n_in,
                              void* d_out, int out_size) {
    const float* x   = (const float*)d_in[0];
    const void*  ei  = d_in[1];
    const float* W1  = (const float*)d_in[2];
    const float* b1  = (const float*)d_in[3];
    const float* W2  = (const float*)d_in[4];
    const float* b2  = (const float*)d_in[5];
    float* out       = (float*)d_out;

    const int n = in_sizes[0] / DD;   // 50000
    const int E = in_sizes[1] / 2;    // 800000 (element count, either dtype)

    float *agg, *dinv, *nrm;
    __half* h;
    int *deg, *off, *bsum, *nsrc, *is64;
    uint2 *wf1, *wf2;
    cudaGetSymbolAddress((void**)&h, g_h);
    cudaGetSymbolAddress((void**)&agg, g_agg);
    cudaGetSymbolAddress((void**)&deg, g_deg);
    cudaGetSymbolAddress((void**)&off, g_off);
    cudaGetSymbolAddress((void**)&bsum, g_bsum);
    cudaGetSymbolAddress((void**)&nsrc, g_nsrc);
    cudaGetSymbolAddress((void**)&nrm, g_nrm);
    cudaGetSymbolAddress((void**)&dinv, g_dinv);
    cudaGetSymbolAddress((void**)&is64, g_is64);
    cudaGetSymbolAddress((void**)&wf1, g_wf1);
    cudaGetSymbolAddress((void**)&wf2, g_wf2);

    const int T = 256;
    const int gN    = (n + T - 1) / T;
    const int gE    = (E + T - 1) / T;
    const int gRowT = (n + 127) / 128;        // tf32 gemm tiles
    const int gWarp = (n * 32 + T - 1) / T;   // warp per node
    const int nbScan = (n + SCAN_B - 1) / SCAN_B;

    // ---- edge dtype detection + CSR build (by dst) ----
    pre_k<<<gN, T>>>(deg, is64, n);
    detect_k<<<gE, T>>>((const int*)ei, E, is64);
    count_k<<<gE, T>>>(ei, is64, deg, E);
    scan_block_k<<<nbScan, SCAN_B>>>(deg, off, bsum, n);
    scan_add_dinv_k<<<gN, T>>>(off, bsum, deg, dinv, n, E, nbScan);
    scatter_k<<<gE, T>>>(ei, is64, off, deg, dinv, nsrc, nrm, E);

    // ---- weight fragment pre-swizzle (both layers, one launch) ----
    wfrag_k<<<64, T>>>(W1, W2, wf1, wf2);

    // ---- layer 1 ----
    gemm_tf32_k<<<gRowT, T>>>(x, wf1, h, n);
    gather_k<<<gWarp, T>>>(off, nsrc, nrm, h, dinv, b1, agg, n);

    // ---- layer 2 ----
    gemm_tf32_k<<<gRowT, T>>>(agg, wf2, h, n);
    gather_k<<<gWarp, T>>>(off, nsrc, nrm, h, dinv, b2, out, n);
}

// round 12
// speedup vs baseline: 1.6106x; 1.2039x over previous
#include <cuda_runtime.h>
#include <cuda_fp16.h>
#include <cstdint>

#define DD 128
#define NMAX 50000
#define EMAX 800000
#define SCAN_B 1024
#define SCAN_NB ((NMAX + SCAN_B - 1) / SCAN_B)   // 49

// Scratch (device globals: no allocation allowed)
__device__ __half g_h[(size_t)NMAX * DD];    // GEMM output in fp16 (12.8MB)
__device__ __half g_agg[(size_t)NMAX * DD];  // layer-1 aggregated+relu'd (fp16)
__device__ int   g_deg[NMAX];                // degree count, then scatter cursor
__device__ int   g_off[NMAX + 1];            // CSR row offsets (by dst)
__device__ int   g_bsum[SCAN_NB + 1];        // scan block sums
__device__ int   g_ctr;                      // scan completion counter
__device__ int   g_nsrc[EMAX];               // dst-sorted source node ids
__device__ float g_nrm[EMAX];                // per-edge norm dinv[src]*dinv[dst]
__device__ float g_dinv[NMAX];               // (deg+1)^{-1/2}
__device__ int   g_is64;                     // 1 if edge_index is int64
__device__ uint2 g_wf1[16 * 16 * 32];        // W1 tf32 b-fragments (64KB)
__device__ uint2 g_wf2[16 * 16 * 32];        // W2 tf32 b-fragments

__device__ __forceinline__ uint32_t f2tf32(float f) {
    uint32_t o;
    asm("cvt.rna.tf32.f32 %0, %1;" : "=r"(o) : "f"(f));
    return o;
}

__device__ __forceinline__ int edge_id(const void* ei, const int* flag, int idx) {
    if (*flag) return (int)((const long long*)ei)[idx];
    return ((const int*)ei)[idx];
}

__device__ __forceinline__ float ld_as_float(const float* p) { return *p; }
__device__ __forceinline__ float ld_as_float(const __half* p) { return __half2float(*p); }

// ---------------------------------------------------------------------------
__global__ void pre_k(int* deg, int* flag, int* ctr, int n) {
    int i = blockIdx.x * blockDim.x + threadIdx.x;
    if (i < n) deg[i] = 0;
    if (i == 0) { *flag = 1; *ctr = 0; }
}

// Sampled dtype detection: int64 => ALL odd 32-bit words are zero. Checking
// 4096 odd words of random int32 node-ids misfires with P ~ (2e-5)^4096 ~ 0.
__global__ void detect_k(const int* __restrict__ w, int E, int* flag) {
    int e = blockIdx.x * blockDim.x + threadIdx.x;
    int m = (E < 4096) ? E : 4096;
    if (e < m && w[2 * e + 1] != 0) *flag = 0;  // benign race: only writes 0
}

__global__ void count_k(const void* __restrict__ ei, const int* __restrict__ flag,
                        int* __restrict__ deg, int E) {
    int e = blockIdx.x * blockDim.x + threadIdx.x;
    if (e < E) atomicAdd(&deg[edge_id(ei, flag, E + e)], 1);
}

// Fused scan: per-block shfl scan + device-wide counter sync + prefix add +
// dinv + cursor reset + sentinel. All 49 blocks co-resident (<=148 SMs).
__global__ void scan_fused_k(int* __restrict__ deg, int* __restrict__ off,
                             float* __restrict__ dinv, int* __restrict__ bsum,
                             int* __restrict__ ctr, int n, int E, int nb) {
    __shared__ int wsum[32];
    __shared__ int bpref;
    const int t = threadIdx.x, b = blockIdx.x;
    const int i = b * SCAN_B + t;
    const int v = (i < n) ? deg[i] : 0;
    const int lane = t & 31, w = t >> 5;

    int s = v;  // inclusive warp scan
#pragma unroll
    for (int d = 1; d < 32; d <<= 1) {
        int x = __shfl_up_sync(0xFFFFFFFFu, s, d);
        if (lane >= d) s += x;
    }
    if (lane == 31) wsum[w] = s;
    __syncthreads();
    if (w == 0) {
        int ws = wsum[lane];
#pragma unroll
        for (int d = 1; d < 32; d <<= 1) {
            int x = __shfl_up_sync(0xFFFFFFFFu, ws, d);
            if (lane >= d) ws += x;
        }
        wsum[lane] = ws;
    }
    __syncthreads();
    const int incl = s + ((w > 0) ? wsum[w - 1] : 0);

    if (t == SCAN_B - 1) {            // publish block total
        bsum[b] = incl;
        __threadfence();
        atomicAdd(ctr, 1);
    }
    if (t == 0) {                     // wait for all totals, build my prefix
        while (atomicAdd(ctr, 0) < nb) { }
        __threadfence();
        int run = 0;
        for (int j = 0; j < b; j++) run += bsum[j];
        bpref = run;
    }
    __syncthreads();

    if (i < n) {
        off[i] = incl - v + bpref;          // exclusive global offset
        dinv[i] = rsqrtf((float)(v + 1));   // +1 self-loop
        deg[i] = 0;                         // cursor for scatter (aliased OK)
    }
    if (b == 0 && t == 0) off[n] = E;
}

// Bucket edges by dst; precompute per-edge normalization
__global__ void scatter_k(const void* __restrict__ ei, const int* __restrict__ flag,
                          const int* __restrict__ off, int* __restrict__ cur,
                          const float* __restrict__ dinv,
                          int* __restrict__ nsrc, float* __restrict__ nrm, int E) {
    int e = blockIdx.x * blockDim.x + threadIdx.x;
    if (e >= E) return;
    int s = edge_id(ei, flag, e);
    int d = edge_id(ei, flag, E + e);
    int pos = off[d] + atomicAdd(&cur[d], 1);
    nsrc[pos] = s;
    nrm[pos] = dinv[s] * dinv[d];
}

// ---------------------------------------------------------------------------
// Pre-swizzle both W matrices into mma b-fragment layout (fused launch).
__global__ void wfrag_k(const float* __restrict__ W1, const float* __restrict__ W2,
                        uint2* __restrict__ wf1, uint2* __restrict__ wf2) {
    int idx = blockIdx.x * blockDim.x + threadIdx.x;
    if (idx >= 16384) return;
    const float* W = (idx < 8192) ? W1 : W2;
    uint2* wf = (idx < 8192) ? wf1 : wf2;
    int id = idx & 8191;
    int lane = id & 31;
    int nt = (id >> 5) & 15;
    int ks = id >> 9;
    int tig = lane & 3, gid = lane >> 2;
    int nn = nt * 8 + gid;
    int k0 = ks * 8 + tig;
    wf[id] = make_uint2(f2tf32(W[k0 * DD + nn]), f2tf32(W[(k0 + 4) * DD + nn]));
}

// H[n,128] = X @ W via mma.sync.m16n8k8 tf32; output stored as fp16.
// InT = float (layer 1 input) or __half (layer-2 activations).
template <typename InT>
__global__ __launch_bounds__(256) void gemm_tf32_k(const InT* __restrict__ X,
                                                   const uint2* __restrict__ wf,
                                                   __half* __restrict__ H, int n) {
    __shared__ uint2 Wsm[8 * 16 * 32];  // 32 KB
    const int tid = threadIdx.x;
    const int wid = tid >> 5;
    const int lane = tid & 31;
    const int tig = lane & 3, gid = lane >> 2;

    const int row0 = blockIdx.x * 128 + wid * 16 + gid;  // this thread: row0, row0+8
    const int r0 = min(row0, n - 1);
    const int r1 = min(row0 + 8, n - 1);
    const InT* x0 = X + (size_t)r0 * DD;
    const InT* x1 = X + (size_t)r1 * DD;

    float c[16][4];
#pragma unroll
    for (int nt = 0; nt < 16; nt++)
#pragma unroll
        for (int q = 0; q < 4; q++) c[nt][q] = 0.f;

#pragma unroll
    for (int half = 0; half < 2; half++) {
        __syncthreads();
        const uint4* srcp = (const uint4*)(wf + half * 4096);
        uint4* dstp = (uint4*)Wsm;
#pragma unroll
        for (int i = tid; i < 2048; i += 256) dstp[i] = srcp[i];
        __syncthreads();

#pragma unroll
        for (int ks = 0; ks < 8; ks++) {
            const int k = half * 64 + ks * 8;
            uint32_t a0 = f2tf32(ld_as_float(x0 + k + tig));
            uint32_t a1 = f2tf32(ld_as_float(x1 + k + tig));
            uint32_t a2 = f2tf32(ld_as_float(x0 + k + tig + 4));
            uint32_t a3 = f2tf32(ld_as_float(x1 + k + tig + 4));
#pragma unroll
            for (int nt = 0; nt < 16; nt++) {
                uint2 b = Wsm[(ks * 16 + nt) * 32 + lane];
                asm volatile(
                    "mma.sync.aligned.m16n8k8.row.col.f32.tf32.tf32.f32 "
                    "{%0,%1,%2,%3}, {%4,%5,%6,%7}, {%8,%9}, {%0,%1,%2,%3};"
                    : "+f"(c[nt][0]), "+f"(c[nt][1]), "+f"(c[nt][2]), "+f"(c[nt][3])
                    : "r"(a0), "r"(a1), "r"(a2), "r"(a3), "r"(b.x), "r"(b.y));
            }
        }
    }

    if (row0 < n) {
        __half2* p = (__half2*)(H + (size_t)row0 * DD);
#pragma unroll
        for (int nt = 0; nt < 16; nt++)
            p[nt * 4 + tig] = __floats2half2_rn(c[nt][0], c[nt][1]);
    }
    if (row0 + 8 < n) {
        __half2* p = (__half2*)(H + (size_t)(row0 + 8) * DD);
#pragma unroll
        for (int nt = 0; nt < 16; nt++)
            p[nt * 4 + tig] = __floats2half2_rn(c[nt][2], c[nt][3]);
    }
}

// ---------------------------------------------------------------------------
// Warp per node, H fp16, unroll-4: lane covers 4 feature cols; 4 edges in
// flight; fp32 accumulation; OutT float (final) or __half (layer 1).
template <typename OutT>
__global__ void gather_k(const int* __restrict__ off, const int* __restrict__ nsrc,
                         const float* __restrict__ nrm, const __half* __restrict__ H,
                         const float* __restrict__ dinv, const float* __restrict__ b,
                         OutT* __restrict__ OUT, int n) {
    int gt = blockIdx.x * blockDim.x + threadIdx.x;
    int i = gt >> 5;
    if (i >= n) return;
    int lane = gt & 31;

    float s = __ldg(&dinv[i]);
    s = s * s;
    float4 acc0 = __ldg(((const float4*)b) + lane);
    {
        const __half2* hp = ((const __half2*)(H + (size_t)i * DD)) + lane * 2;
        float2 h0 = __half22float2(__ldg(hp));
        float2 h1 = __half22float2(__ldg(hp + 1));
        acc0.x += h0.x * s; acc0.y += h0.y * s;
        acc0.z += h1.x * s; acc0.w += h1.y * s;
    }
    float4 acc1 = make_float4(0.f, 0.f, 0.f, 0.f);

    const int end = off[i + 1];
    int j = off[i];
    for (; j + 4 <= end; j += 4) {
        int   s0 = __ldg(&nsrc[j]),     s1 = __ldg(&nsrc[j + 1]);
        int   s2 = __ldg(&nsrc[j + 2]), s3 = __ldg(&nsrc[j + 3]);
        float w0 = __ldg(&nrm[j]),      w1 = __ldg(&nrm[j + 1]);
        float w2 = __ldg(&nrm[j + 2]),  w3 = __ldg(&nrm[j + 3]);
        const __half2* p0 = ((const __half2*)(H + (size_t)s0 * DD)) + lane * 2;
        const __half2* p1 = ((const __half2*)(H + (size_t)s1 * DD)) + lane * 2;
        const __half2* p2 = ((const __half2*)(H + (size_t)s2 * DD)) + lane * 2;
        const __half2* p3 = ((const __half2*)(H + (size_t)s3 * DD)) + lane * 2;
        __half2 a0 = __ldg(p0), b0 = __ldg(p0 + 1);
        __half2 a1 = __ldg(p1), b1 = __ldg(p1 + 1);
        __half2 a2 = __ldg(p2), b2 = __ldg(p2 + 1);
        __half2 a3 = __ldg(p3), b3 = __ldg(p3 + 1);
        float2 f0 = __half22float2(a0), g0 = __half22float2(b0);
        float2 f1 = __half22float2(a1), g1 = __half22float2(b1);
        float2 f2 = __half22float2(a2), g2 = __half22float2(b2);
        float2 f3 = __half22float2(a3), g3 = __half22float2(b3);
        acc0.x += f0.x * w0; acc0.y += f0.y * w0; acc0.z += g0.x * w0; acc0.w += g0.y * w0;
        acc1.x += f1.x * w1; acc1.y += f1.y * w1; acc1.z += g1.x * w1; acc1.w += g1.y * w1;
        acc0.x += f2.x * w2; acc0.y += f2.y * w2; acc0.z += g2.x * w2; acc0.w += g2.y * w2;
        acc1.x += f3.x * w3; acc1.y += f3.y * w3; acc1.z += g3.x * w3; acc1.w += g3.y * w3;
    }
    for (; j < end; j++) {
        int   s0 = __ldg(&nsrc[j]);
        float w0 = __ldg(&nrm[j]);
        const __half2* p0 = ((const __half2*)(H + (size_t)s0 * DD)) + lane * 2;
        float2 f0 = __half22float2(__ldg(p0));
        float2 g0 = __half22float2(__ldg(p0 + 1));
        acc0.x += f0.x * w0; acc0.y += f0.y * w0; acc0.z += g0.x * w0; acc0.w += g0.y * w0;
    }
    acc0.x = fmaxf(acc0.x + acc1.x, 0.f);
    acc0.y = fmaxf(acc0.y + acc1.y, 0.f);
    acc0.z = fmaxf(acc0.z + acc1.z, 0.f);
    acc0.w = fmaxf(acc0.w + acc1.w, 0.f);

    if (sizeof(OutT) == 4) {  // fp32 final output
        ((float4*)((float*)OUT + (size_t)i * DD))[lane] = acc0;
    } else {                  // fp16 intermediate activations
        __half2 h01 = __floats2half2_rn(acc0.x, acc0.y);
        __half2 h23 = __floats2half2_rn(acc0.z, acc0.w);
        uint2 u;
        u.x = reinterpret_cast<uint32_t&>(h01);
        u.y = reinterpret_cast<uint32_t&>(h23);
        ((uint2*)((__half*)OUT + (size_t)i * DD))[lane] = u;
    }
}

// ---------------------------------------------------------------------------
extern "C" void kernel_launch(void* const* d_in, const int* in_sizes, int n_in,
                              void* d_out, int out_size) {
    const float* x   = (const float*)d_in[0];
    const void*  ei  = d_in[1];
    const float* W1  = (const float*)d_in[2];
    const float* b1  = (const float*)d_in[3];
    const float* W2  = (const float*)d_in[4];
    const float* b2  = (const float*)d_in[5];
    float* out       = (float*)d_out;

    const int n = in_sizes[0] / DD;   // 50000
    const int E = in_sizes[1] / 2;    // 800000 (element count, either dtype)

    float *dinv, *nrm;
    __half *h, *agg;
    int *deg, *off, *bsum, *ctr, *nsrc, *is64;
    uint2 *wf1, *wf2;
    cudaGetSymbolAddress((void**)&h, g_h);
    cudaGetSymbolAddress((void**)&agg, g_agg);
    cudaGetSymbolAddress((void**)&deg, g_deg);
    cudaGetSymbolAddress((void**)&off, g_off);
    cudaGetSymbolAddress((void**)&bsum, g_bsum);
    cudaGetSymbolAddress((void**)&ctr, g_ctr);
    cudaGetSymbolAddress((void**)&nsrc, g_nsrc);
    cudaGetSymbolAddress((void**)&nrm, g_nrm);
    cudaGetSymbolAddress((void**)&dinv, g_dinv);
    cudaGetSymbolAddress((void**)&is64, g_is64);
    cudaGetSymbolAddress((void**)&wf1, g_wf1);
    cudaGetSymbolAddress((void**)&wf2, g_wf2);

    const int T = 256;
    const int gN    = (n + T - 1) / T;
    const int gE    = (E + T - 1) / T;
    const int gRowT = (n + 127) / 128;        // tf32 gemm tiles
    const int gWarp = (n * 32 + T - 1) / T;   // warp per node
    const int nbScan = (n + SCAN_B - 1) / SCAN_B;

    // ---- edge dtype detection + CSR build (by dst) ----
    pre_k<<<gN, T>>>(deg, is64, ctr, n);
    detect_k<<<16, T>>>((const int*)ei, E, is64);
    count_k<<<gE, T>>>(ei, is64, deg, E);
    scan_fused_k<<<nbScan, SCAN_B>>>(deg, off, dinv, bsum, ctr, n, E, nbScan);
    scatter_k<<<gE, T>>>(ei, is64, off, deg, dinv, nsrc, nrm, E);

    // ---- weight fragment pre-swizzle (both layers, one launch) ----
    wfrag_k<<<64, T>>>(W1, W2, wf1, wf2);

    // ---- layer 1 ----
    gemm_tf32_k<float><<<gRowT, T>>>(x, wf1, h, n);
    gather_k<__half><<<gWarp, T>>>(off, nsrc, nrm, h, dinv, b1, agg, n);

    // ---- layer 2 ----
    gemm_tf32_k<__half><<<gRowT, T>>>(agg, wf2, h, n);
    gather_k<float><<<gWarp, T>>>(off, nsrc, nrm, h, dinv, b2, out, n);
}